// round 1
// baseline (speedup 1.0000x reference)
#include <cuda_runtime.h>
#include <math.h>

#define D_MODEL 1024
#define D_MID   4096
#define SEQ     2048
#define BATCH   2
#define NTOK    (BATCH * SEQ)   // 4096
#define NH      16
#define HD      64

// ---------------- persistent scratch (no cudaMalloc allowed) ----------------
__device__ float g_nx  [NTOK * D_MODEL];       // 16 MB (reused for both LNs)
__device__ float g_qkv [NTOK * 3 * D_MODEL];   // 48 MB
__device__ float g_ctx [NTOK * D_MODEL];       // 16 MB
__device__ float g_x1  [NTOK * D_MODEL];       // 16 MB
__device__ float g_hid [NTOK * D_MID];         // 64 MB

// ---------------- layernorm: one block per row ----------------
__global__ void __launch_bounds__(256) ln_kernel(
    const float* __restrict__ x, const float* __restrict__ g,
    const float* __restrict__ bta, float* __restrict__ o)
{
    __shared__ float rbuf[16];
    const int row = blockIdx.x;
    const int tid = threadIdx.x;
    const float4* xr = (const float4*)(x + (size_t)row * D_MODEL);
    float4 v = xr[tid];
    float s  = v.x + v.y + v.z + v.w;
    float sq = v.x*v.x + v.y*v.y + v.z*v.z + v.w*v.w;
    #pragma unroll
    for (int off = 16; off; off >>= 1) {
        s  += __shfl_xor_sync(0xffffffffu, s,  off);
        sq += __shfl_xor_sync(0xffffffffu, sq, off);
    }
    const int wid = tid >> 5, lane = tid & 31;
    if (lane == 0) { rbuf[wid] = s; rbuf[8 + wid] = sq; }
    __syncthreads();
    if (tid < 32) {
        float a  = (lane < 8) ? rbuf[lane]     : 0.f;
        float b2 = (lane < 8) ? rbuf[8 + lane] : 0.f;
        #pragma unroll
        for (int off = 4; off; off >>= 1) {
            a  += __shfl_xor_sync(0xffffffffu, a,  off);
            b2 += __shfl_xor_sync(0xffffffffu, b2, off);
        }
        if (lane == 0) { rbuf[0] = a; rbuf[8] = b2; }
    }
    __syncthreads();
    const float mu  = rbuf[0] * (1.f / D_MODEL);
    const float var = rbuf[8] * (1.f / D_MODEL) - mu * mu;
    const float rs  = rsqrtf(var + 1e-5f);
    float4 gv = ((const float4*)g)[tid];
    float4 bv = ((const float4*)bta)[tid];
    float4 o4;
    o4.x = (v.x - mu) * rs * gv.x + bv.x;
    o4.y = (v.y - mu) * rs * gv.y + bv.y;
    o4.z = (v.z - mu) * rs * gv.z + bv.z;
    o4.w = (v.w - mu) * rs * gv.w + bv.w;
    ((float4*)(o + (size_t)row * D_MODEL))[tid] = o4;
}

// ---------------- gelu ----------------
__device__ __forceinline__ float gelu_f(float x)
{
    const float c = 0.7978845608028654f;   // sqrt(2/pi)
    float x3 = x * x * x;
    return 0.5f * x * (1.f + tanhf(c * (x + 0.044715f * x3)));
}

// ---------------- fp32 SGEMM: C[M,N] = A[M,K] @ B[K,N] + bias (+R) (gelu?) ----
// 128x128 block tile, BK=8, 256 threads, 8x8 per thread.
template<bool GELU_ACT, bool RESID>
__global__ void __launch_bounds__(256) sgemm_kernel(
    const float* __restrict__ A, const float* __restrict__ B,
    const float* __restrict__ bias, const float* __restrict__ R,
    float* __restrict__ C, int M, int N, int K)
{
    __shared__ float As[8][128];
    __shared__ float Bs[8][128];
    const int tid = threadIdx.x;
    const int bm = blockIdx.y * 128;
    const int bn = blockIdx.x * 128;
    const int arow = tid >> 1;
    const int acol = (tid & 1) << 2;
    const int brow = tid >> 5;
    const int bcol = (tid & 31) << 2;
    const int tx = tid & 15, ty = tid >> 4;

    const float* Aptr = A + (size_t)(bm + arow) * K + acol;
    const float* Bptr = B + (size_t)brow * N + bn + bcol;

    float acc[8][8];
    #pragma unroll
    for (int i = 0; i < 8; i++)
        #pragma unroll
        for (int j = 0; j < 8; j++) acc[i][j] = 0.f;

    for (int k0 = 0; k0 < K; k0 += 8) {
        float4 av = *(const float4*)(Aptr + k0);
        float4 bv = *(const float4*)(Bptr + (size_t)k0 * N);
        As[acol + 0][arow] = av.x;
        As[acol + 1][arow] = av.y;
        As[acol + 2][arow] = av.z;
        As[acol + 3][arow] = av.w;
        *(float4*)&Bs[brow][bcol] = bv;
        __syncthreads();
        #pragma unroll
        for (int kk = 0; kk < 8; kk++) {
            float4 a0 = *(const float4*)&As[kk][ty * 8];
            float4 a1 = *(const float4*)&As[kk][ty * 8 + 4];
            float4 b0 = *(const float4*)&Bs[kk][tx * 8];
            float4 b1 = *(const float4*)&Bs[kk][tx * 8 + 4];
            float ar[8] = {a0.x, a0.y, a0.z, a0.w, a1.x, a1.y, a1.z, a1.w};
            float br[8] = {b0.x, b0.y, b0.z, b0.w, b1.x, b1.y, b1.z, b1.w};
            #pragma unroll
            for (int i = 0; i < 8; i++)
                #pragma unroll
                for (int j = 0; j < 8; j++)
                    acc[i][j] = fmaf(ar[i], br[j], acc[i][j]);
        }
        __syncthreads();
    }

    #pragma unroll
    for (int i = 0; i < 8; i++) {
        const int row = bm + ty * 8 + i;
        float* crow = C + (size_t)row * N;
        const float* rrow = RESID ? (R + (size_t)row * N) : nullptr;
        #pragma unroll
        for (int jj = 0; jj < 8; jj += 4) {
            const int col = bn + tx * 8 + jj;
            float4 bsv = *(const float4*)&bias[col];
            float4 c;
            c.x = acc[i][jj + 0] + bsv.x;
            c.y = acc[i][jj + 1] + bsv.y;
            c.z = acc[i][jj + 2] + bsv.z;
            c.w = acc[i][jj + 3] + bsv.w;
            if (RESID) {
                float4 rv = *(const float4*)&rrow[col];
                c.x += rv.x; c.y += rv.y; c.z += rv.z; c.w += rv.w;
            }
            if (GELU_ACT) {
                c.x = gelu_f(c.x); c.y = gelu_f(c.y);
                c.z = gelu_f(c.z); c.w = gelu_f(c.w);
            }
            *(float4*)&crow[col] = c;
        }
    }
}

// ---------------- flash attention (fp32, 64x64 tiles, online softmax) -------
// grid: (SEQ/64, NH, BATCH), block 256.  qkv: [NTOK, 3*D_MODEL] rows.
// smem rows padded to 68 floats (272 B) so LDS.128 across 4-row strides hit
// distinct 16B quad-banks.
#define ALD 68
#define ATT_SMEM (4 * 64 * ALD * 4)

__global__ void __launch_bounds__(256) attn_kernel(
    const float* __restrict__ qkv, float* __restrict__ ctx)
{
    extern __shared__ float sm[];
    float* Qs = sm;
    float* Ks = Qs + 64 * ALD;
    float* Vs = Ks + 64 * ALD;
    float* Ps = Vs + 64 * ALD;

    const int qt = blockIdx.x, h = blockIdx.y, b = blockIdx.z;
    const int q0 = qt * 64;
    const int tid = threadIdx.x;
    const int tx = tid & 15, ty = tid >> 4;

    const size_t rowbase = (size_t)(b * SEQ) * (3 * D_MODEL);
    const int qcol = h * HD;
    const int kcol = D_MODEL + h * HD;
    const int vcol = 2 * D_MODEL + h * HD;

    // load Q tile, pre-scaled by 1/sqrt(D_MODEL) = 1/32
    #pragma unroll
    for (int t = 0; t < 4; t++) {
        int lin = tid + t * 256;           // 0..1023
        int r = lin >> 4, d4 = (lin & 15) << 2;
        float4 v = *(const float4*)&qkv[rowbase + (size_t)(q0 + r) * (3 * D_MODEL) + qcol + d4];
        v.x *= 0.03125f; v.y *= 0.03125f; v.z *= 0.03125f; v.w *= 0.03125f;
        *(float4*)&Qs[r * ALD + d4] = v;
    }

    float m[4], l[4], acc[4][4];
    #pragma unroll
    for (int i = 0; i < 4; i++) {
        m[i] = -INFINITY; l[i] = 0.f;
        #pragma unroll
        for (int j = 0; j < 4; j++) acc[i][j] = 0.f;
    }

    for (int jt = 0; jt <= qt; jt++) {
        const int j0 = jt * 64;
        #pragma unroll
        for (int t = 0; t < 4; t++) {
            int lin = tid + t * 256;
            int r = lin >> 4, d4 = (lin & 15) << 2;
            size_t base = rowbase + (size_t)(j0 + r) * (3 * D_MODEL);
            *(float4*)&Ks[r * ALD + d4] = *(const float4*)&qkv[base + kcol + d4];
            *(float4*)&Vs[r * ALD + d4] = *(const float4*)&qkv[base + vcol + d4];
        }
        __syncthreads();

        // S = Q K^T  (thread owns q rows ty+16i, k rows tx+16j)
        float s[4][4];
        #pragma unroll
        for (int i = 0; i < 4; i++)
            #pragma unroll
            for (int j = 0; j < 4; j++) s[i][j] = 0.f;

        #pragma unroll 4
        for (int d = 0; d < HD; d += 4) {
            float4 qv[4], kv[4];
            #pragma unroll
            for (int i = 0; i < 4; i++) qv[i] = *(const float4*)&Qs[(ty + 16 * i) * ALD + d];
            #pragma unroll
            for (int j = 0; j < 4; j++) kv[j] = *(const float4*)&Ks[(tx + 16 * j) * ALD + d];
            #pragma unroll
            for (int i = 0; i < 4; i++)
                #pragma unroll
                for (int j = 0; j < 4; j++) {
                    s[i][j] = fmaf(qv[i].x, kv[j].x, s[i][j]);
                    s[i][j] = fmaf(qv[i].y, kv[j].y, s[i][j]);
                    s[i][j] = fmaf(qv[i].z, kv[j].z, s[i][j]);
                    s[i][j] = fmaf(qv[i].w, kv[j].w, s[i][j]);
                }
        }

        if (jt == qt) {     // causal mask on diagonal tile
            #pragma unroll
            for (int i = 0; i < 4; i++)
                #pragma unroll
                for (int j = 0; j < 4; j++)
                    if ((j0 + tx + 16 * j) > (q0 + ty + 16 * i)) s[i][j] = -INFINITY;
        }

        // online softmax per row (row owned by 16 consecutive lanes)
        #pragma unroll
        for (int i = 0; i < 4; i++) {
            float mx = fmaxf(fmaxf(s[i][0], s[i][1]), fmaxf(s[i][2], s[i][3]));
            #pragma unroll
            for (int off = 8; off; off >>= 1)
                mx = fmaxf(mx, __shfl_xor_sync(0xffffffffu, mx, off));
            const float mn = fmaxf(m[i], mx);
            const float alpha = expf(m[i] - mn);
            float p[4], psum = 0.f;
            #pragma unroll
            for (int j = 0; j < 4; j++) { p[j] = expf(s[i][j] - mn); psum += p[j]; }
            #pragma unroll
            for (int off = 8; off; off >>= 1)
                psum += __shfl_xor_sync(0xffffffffu, psum, off);
            l[i] = l[i] * alpha + psum;
            m[i] = mn;
            #pragma unroll
            for (int j = 0; j < 4; j++) {
                acc[i][j] *= alpha;
                Ps[(ty + 16 * i) * ALD + tx + 16 * j] = p[j];
            }
        }
        __syncthreads();

        // O += P @ V   (thread owns out cols tx*4..+3)
        #pragma unroll 4
        for (int kk = 0; kk < 64; kk += 4) {
            float4 p4[4];
            #pragma unroll
            for (int i = 0; i < 4; i++) p4[i] = *(const float4*)&Ps[(ty + 16 * i) * ALD + kk];
            float4 v0 = *(const float4*)&Vs[(kk + 0) * ALD + tx * 4];
            float4 v1 = *(const float4*)&Vs[(kk + 1) * ALD + tx * 4];
            float4 v2 = *(const float4*)&Vs[(kk + 2) * ALD + tx * 4];
            float4 v3 = *(const float4*)&Vs[(kk + 3) * ALD + tx * 4];
            float vr[4][4] = {{v0.x, v0.y, v0.z, v0.w}, {v1.x, v1.y, v1.z, v1.w},
                              {v2.x, v2.y, v2.z, v2.w}, {v3.x, v3.y, v3.z, v3.w}};
            #pragma unroll
            for (int i = 0; i < 4; i++) {
                float pr[4] = {p4[i].x, p4[i].y, p4[i].z, p4[i].w};
                #pragma unroll
                for (int j = 0; j < 4; j++) {
                    acc[i][j] = fmaf(pr[0], vr[0][j], acc[i][j]);
                    acc[i][j] = fmaf(pr[1], vr[1][j], acc[i][j]);
                    acc[i][j] = fmaf(pr[2], vr[2][j], acc[i][j]);
                    acc[i][j] = fmaf(pr[3], vr[3][j], acc[i][j]);
                }
            }
        }
        __syncthreads();
    }

    // normalize + store: ctx[token, h*64 + d]
    #pragma unroll
    for (int i = 0; i < 4; i++) {
        const float inv = 1.f / l[i];
        float4 o;
        o.x = acc[i][0] * inv; o.y = acc[i][1] * inv;
        o.z = acc[i][2] * inv; o.w = acc[i][3] * inv;
        const size_t tok = (size_t)(b * SEQ + q0 + ty + 16 * i);
        *(float4*)&ctx[tok * D_MODEL + h * HD + tx * 4] = o;
    }
}

// ---------------- host launch ----------------
extern "C" void kernel_launch(void* const* d_in, const int* in_sizes, int n_in,
                              void* d_out, int out_size)
{
    const float* x    = (const float*)d_in[0];
    const float* wqkv = (const float*)d_in[1];
    const float* bqkv = (const float*)d_in[2];
    const float* wo   = (const float*)d_in[3];
    const float* bo   = (const float*)d_in[4];
    const float* g1   = (const float*)d_in[5];
    const float* be1  = (const float*)d_in[6];
    const float* g2   = (const float*)d_in[7];
    const float* be2  = (const float*)d_in[8];
    const float* w1   = (const float*)d_in[9];
    const float* b1   = (const float*)d_in[10];
    const float* w2   = (const float*)d_in[11];
    const float* b2   = (const float*)d_in[12];
    float* out = (float*)d_out;

    float *nx, *qkv, *ctx, *x1, *hid;
    cudaGetSymbolAddress((void**)&nx,  g_nx);
    cudaGetSymbolAddress((void**)&qkv, g_qkv);
    cudaGetSymbolAddress((void**)&ctx, g_ctx);
    cudaGetSymbolAddress((void**)&x1,  g_x1);
    cudaGetSymbolAddress((void**)&hid, g_hid);

    cudaFuncSetAttribute(attn_kernel, cudaFuncAttributeMaxDynamicSharedMemorySize, ATT_SMEM);

    // 1. LN1
    ln_kernel<<<NTOK, 256>>>(x, g1, be1, nx);
    // 2. QKV projection: [4096,1024] @ [1024,3072] + b
    sgemm_kernel<false, false><<<dim3(3 * D_MODEL / 128, NTOK / 128), 256>>>(
        nx, wqkv, bqkv, nullptr, qkv, NTOK, 3 * D_MODEL, D_MODEL);
    // 3. attention
    attn_kernel<<<dim3(SEQ / 64, NH, BATCH), 256, ATT_SMEM>>>(qkv, ctx);
    // 4. O projection + residual: x1 = x + ctx@wo + bo
    sgemm_kernel<false, true><<<dim3(D_MODEL / 128, NTOK / 128), 256>>>(
        ctx, wo, bo, x, x1, NTOK, D_MODEL, D_MODEL);
    // 5. LN2
    ln_kernel<<<NTOK, 256>>>(x1, g2, be2, nx);
    // 6. FFN1 + gelu: hid = gelu(nx@w1 + b1)
    sgemm_kernel<true, false><<<dim3(D_MID / 128, NTOK / 128), 256>>>(
        nx, w1, b1, nullptr, hid, NTOK, D_MID, D_MODEL);
    // 7. FFN2 + residual: out = x1 + hid@w2 + b2
    sgemm_kernel<false, true><<<dim3(D_MODEL / 128, NTOK / 128), 256>>>(
        hid, w2, b2, x1, out, NTOK, D_MODEL, D_MID);
}

// round 2
// speedup vs baseline: 1.7906x; 1.7906x over previous
#include <cuda_runtime.h>
#include <cuda_bf16.h>
#include <math.h>

#define D_MODEL 1024
#define D_MID   4096
#define SEQ     2048
#define BATCH   2
#define NTOK    (BATCH * SEQ)   // 4096
#define NH      16
#define HD      64

// ---------------- persistent scratch (no cudaMalloc allowed) ----------------
__device__ __nv_bfloat16 g_lnh [NTOK * D_MODEL];
__device__ __nv_bfloat16 g_lnl [NTOK * D_MODEL];
__device__ float         g_qkv [NTOK * 3 * D_MODEL];
__device__ __nv_bfloat16 g_ctxh[NTOK * D_MODEL];
__device__ __nv_bfloat16 g_ctxl[NTOK * D_MODEL];
__device__ float         g_x1  [NTOK * D_MODEL];
__device__ __nv_bfloat16 g_hidh[NTOK * D_MID];
__device__ __nv_bfloat16 g_hidl[NTOK * D_MID];
__device__ __nv_bfloat16 g_wqkvh[D_MODEL * 3 * D_MODEL];
__device__ __nv_bfloat16 g_wqkvl[D_MODEL * 3 * D_MODEL];
__device__ __nv_bfloat16 g_woh [D_MODEL * D_MODEL];
__device__ __nv_bfloat16 g_wol [D_MODEL * D_MODEL];
__device__ __nv_bfloat16 g_w1h [D_MODEL * D_MID];
__device__ __nv_bfloat16 g_w1l [D_MODEL * D_MID];
__device__ __nv_bfloat16 g_w2h [D_MID * D_MODEL];
__device__ __nv_bfloat16 g_w2l [D_MID * D_MODEL];

// ---------------- helpers ----------------
__device__ __forceinline__ void split2(float v, __nv_bfloat16& h, __nv_bfloat16& l)
{
    h = __float2bfloat16(v);
    l = __float2bfloat16(v - __bfloat162float(h));
}

__device__ __forceinline__ unsigned smem_u32(const void* p)
{
    return (unsigned)__cvta_generic_to_shared(p);
}

#define CP16(dst_u32, src_ptr) \
    asm volatile("cp.async.cg.shared.global [%0], [%1], 16;\n" :: "r"(dst_u32), "l"(src_ptr))
#define CP_COMMIT() asm volatile("cp.async.commit_group;\n")
#define CP_WAIT(n)  asm volatile("cp.async.wait_group %0;\n" :: "n"(n))

#define LDSM4(r, addr) \
    asm volatile("ldmatrix.sync.aligned.m8n8.x4.shared.b16 {%0,%1,%2,%3},[%4];" \
        : "=r"((r)[0]), "=r"((r)[1]), "=r"((r)[2]), "=r"((r)[3]) : "r"(addr))
#define LDSM4T(r, addr) \
    asm volatile("ldmatrix.sync.aligned.m8n8.x4.trans.shared.b16 {%0,%1,%2,%3},[%4];" \
        : "=r"((r)[0]), "=r"((r)[1]), "=r"((r)[2]), "=r"((r)[3]) : "r"(addr))

#define MMA_BF16(d, a, b0, b1) \
    asm volatile("mma.sync.aligned.m16n8k16.row.col.f32.bf16.bf16.f32 " \
        "{%0,%1,%2,%3},{%4,%5,%6,%7},{%8,%9},{%0,%1,%2,%3};" \
        : "+f"((d)[0]), "+f"((d)[1]), "+f"((d)[2]), "+f"((d)[3]) \
        : "r"((a)[0]), "r"((a)[1]), "r"((a)[2]), "r"((a)[3]), "r"(b0), "r"(b1))

// ---------------- fp32 -> bf16 hi/lo split (weights) ----------------
__global__ void __launch_bounds__(256) split_kernel(
    const float* __restrict__ x, __nv_bfloat16* __restrict__ hi,
    __nv_bfloat16* __restrict__ lo, int n4)
{
    int i = blockIdx.x * 256 + threadIdx.x;
    if (i >= n4) return;
    float4 v = ((const float4*)x)[i];
    __nv_bfloat16 h0, h1, h2, h3, l0, l1, l2, l3;
    split2(v.x, h0, l0); split2(v.y, h1, l1);
    split2(v.z, h2, l2); split2(v.w, h3, l3);
    __nv_bfloat162 a, b;
    a.x = h0; a.y = h1; b.x = h2; b.y = h3;
    ((__nv_bfloat162*)hi)[2 * i]     = a;
    ((__nv_bfloat162*)hi)[2 * i + 1] = b;
    a.x = l0; a.y = l1; b.x = l2; b.y = l3;
    ((__nv_bfloat162*)lo)[2 * i]     = a;
    ((__nv_bfloat162*)lo)[2 * i + 1] = b;
}

// ---------------- layernorm -> bf16 hi/lo ----------------
__global__ void __launch_bounds__(256) ln_kernel(
    const float* __restrict__ x, const float* __restrict__ g,
    const float* __restrict__ bta, __nv_bfloat16* __restrict__ hi,
    __nv_bfloat16* __restrict__ lo)
{
    __shared__ float rbuf[16];
    const int row = blockIdx.x;
    const int tid = threadIdx.x;
    const float4* xr = (const float4*)(x + (size_t)row * D_MODEL);
    float4 v = xr[tid];
    float s  = v.x + v.y + v.z + v.w;
    float sq = v.x*v.x + v.y*v.y + v.z*v.z + v.w*v.w;
    #pragma unroll
    for (int off = 16; off; off >>= 1) {
        s  += __shfl_xor_sync(0xffffffffu, s,  off);
        sq += __shfl_xor_sync(0xffffffffu, sq, off);
    }
    const int wid = tid >> 5, lane = tid & 31;
    if (lane == 0) { rbuf[wid] = s; rbuf[8 + wid] = sq; }
    __syncthreads();
    if (tid < 32) {
        float a  = (lane < 8) ? rbuf[lane]     : 0.f;
        float b2 = (lane < 8) ? rbuf[8 + lane] : 0.f;
        #pragma unroll
        for (int off = 4; off; off >>= 1) {
            a  += __shfl_xor_sync(0xffffffffu, a,  off);
            b2 += __shfl_xor_sync(0xffffffffu, b2, off);
        }
        if (lane == 0) { rbuf[0] = a; rbuf[8] = b2; }
    }
    __syncthreads();
    const float mu  = rbuf[0] * (1.f / D_MODEL);
    const float var = rbuf[8] * (1.f / D_MODEL) - mu * mu;
    const float rs  = rsqrtf(var + 1e-5f);
    float4 gv = ((const float4*)g)[tid];
    float4 bv = ((const float4*)bta)[tid];
    float o0 = (v.x - mu) * rs * gv.x + bv.x;
    float o1 = (v.y - mu) * rs * gv.y + bv.y;
    float o2 = (v.z - mu) * rs * gv.z + bv.z;
    float o3 = (v.w - mu) * rs * gv.w + bv.w;
    __nv_bfloat16 h0, h1, h2, h3, l0, l1, l2, l3;
    split2(o0, h0, l0); split2(o1, h1, l1);
    split2(o2, h2, l2); split2(o3, h3, l3);
    const size_t base = (size_t)row * D_MODEL + tid * 4;
    __nv_bfloat162 p;
    p.x = h0; p.y = h1; *(__nv_bfloat162*)&hi[base]     = p;
    p.x = h2; p.y = h3; *(__nv_bfloat162*)&hi[base + 2] = p;
    p.x = l0; p.y = l1; *(__nv_bfloat162*)&lo[base]     = p;
    p.x = l2; p.y = l3; *(__nv_bfloat162*)&lo[base + 2] = p;
}

// ---------------- gelu ----------------
__device__ __forceinline__ float gelu_f(float x)
{
    const float c = 0.7978845608028654f;
    float x3 = x * x * x;
    return 0.5f * x * (1.f + tanhf(c * (x + 0.044715f * x3)));
}

// ---------------- bf16x3 tensor-core GEMM ----------------
// C[M,N] = A[M,K] @ B[K,N] (+bias) (+R) (gelu?) with A,B given as bf16 hi/lo
// pairs; 3 MMAs per fragment pair: Ah*Bh + Ah*Bl + Al*Bh. fp32 accumulate.
// 128x128 block, BK=64, 8 warps (2 m x 4 n), warp tile 64x32.
// smem: SW128-swizzled; double-buffered cp.async. 131072 B dynamic smem.
#define GSTAGE 65536
#define GSM_AH 0
#define GSM_AL 16384
#define GSM_BH 32768
#define GSM_BL 49152

template<bool GELU_ACT, bool RESID, bool OUTF32, bool SPLIT>
__global__ void __launch_bounds__(256) mma_gemm(
    const __nv_bfloat16* __restrict__ Ah, const __nv_bfloat16* __restrict__ Al,
    const __nv_bfloat16* __restrict__ Bh, const __nv_bfloat16* __restrict__ Bl,
    const float* __restrict__ bias, const float* __restrict__ R,
    float* __restrict__ Cf, __nv_bfloat16* __restrict__ Ch,
    __nv_bfloat16* __restrict__ Cl, int M, int N, int K)
{
    extern __shared__ char smraw[];
    const unsigned sbase = smem_u32(smraw);
    const int tid = threadIdx.x, lane = tid & 31, wid = tid >> 5;
    const int wm = wid & 1, wn = wid >> 1;
    const int bm = blockIdx.y * 128, bn = blockIdx.x * 128;

    float acc[4][4][4];
    #pragma unroll
    for (int i = 0; i < 4; i++)
        #pragma unroll
        for (int j = 0; j < 4; j++)
            #pragma unroll
            for (int q = 0; q < 4; q++) acc[i][j][q] = 0.f;

    // ---- load geometry ----
    const int ar = tid >> 1, ac = (tid & 1) * 4;   // A: 128 rows x 8 chunks
    const int br = tid >> 2, bc = (tid & 3) * 4;   // B: 64 rows x 16 chunks
    unsigned aoff[4], boff[4];
    #pragma unroll
    for (int i = 0; i < 4; i++) {
        aoff[i] = (unsigned)(ar * 128 + (((ac + i) ^ (ar & 7)) << 4));
        boff[i] = (unsigned)(br * 256 + (((bc + i) ^ (br & 7)) << 4));
    }
    const __nv_bfloat16* agh = Ah + (size_t)(bm + ar) * K;
    const __nv_bfloat16* agl = Al + (size_t)(bm + ar) * K;

    auto load_stage = [&](int s, int k0) {
        unsigned sb = sbase + s * GSTAGE;
        const __nv_bfloat16* bgh = Bh + (size_t)(k0 + br) * N + bn;
        const __nv_bfloat16* bgl = Bl + (size_t)(k0 + br) * N + bn;
        #pragma unroll
        for (int i = 0; i < 4; i++) {
            CP16(sb + GSM_AH + aoff[i], agh + k0 + (ac + i) * 8);
            CP16(sb + GSM_AL + aoff[i], agl + k0 + (ac + i) * 8);
            CP16(sb + GSM_BH + boff[i], bgh + (bc + i) * 8);
            CP16(sb + GSM_BL + boff[i], bgl + (bc + i) * 8);
        }
        CP_COMMIT();
    };

    // ---- ldmatrix geometry ----
    const int a_row_l = lane & 15;          // row within 16-row tile
    const int hi_half = (lane >> 4) & 1;    // second 16B chunk
    int a_rowoff[4], a_rmask[4];
    #pragma unroll
    for (int i = 0; i < 4; i++) {
        int r = wm * 64 + i * 16 + a_row_l;
        a_rowoff[i] = r * 128;
        a_rmask[i]  = r & 7;
    }
    const int b_krow_l = lane & 15;
    int b_nchunk[2];
    #pragma unroll
    for (int p = 0; p < 2; p++) b_nchunk[p] = wn * 4 + p * 2 + hi_half;

    const int NIT = K >> 6;
    load_stage(0, 0);

    for (int it = 0; it < NIT; it++) {
        if (it + 1 < NIT) { load_stage((it + 1) & 1, (it + 1) << 6); CP_WAIT(1); }
        else              { CP_WAIT(0); }
        __syncthreads();

        unsigned sb = sbase + (it & 1) * GSTAGE;
        #pragma unroll
        for (int ks = 0; ks < 4; ks++) {
            unsigned ah[4][4], al[4][4], bh[2][4], bl[2][4];
            #pragma unroll
            for (int i = 0; i < 4; i++) {
                int chunk = 2 * ks + hi_half;
                unsigned off = a_rowoff[i] + ((chunk ^ a_rmask[i]) << 4);
                LDSM4(ah[i], sb + GSM_AH + off);
                LDSM4(al[i], sb + GSM_AL + off);
            }
            #pragma unroll
            for (int p = 0; p < 2; p++) {
                int kr = ks * 16 + b_krow_l;
                unsigned off = kr * 256 + ((b_nchunk[p] ^ (kr & 7)) << 4);
                LDSM4T(bh[p], sb + GSM_BH + off);
                LDSM4T(bl[p], sb + GSM_BL + off);
            }
            #pragma unroll
            for (int i = 0; i < 4; i++)
                #pragma unroll
                for (int j = 0; j < 4; j++) {
                    const int p = j >> 1, hf = (j & 1) * 2;
                    MMA_BF16(acc[i][j], ah[i], bh[p][hf], bh[p][hf + 1]);
                    MMA_BF16(acc[i][j], ah[i], bl[p][hf], bl[p][hf + 1]);
                    MMA_BF16(acc[i][j], al[i], bh[p][hf], bh[p][hf + 1]);
                }
        }
        __syncthreads();
    }

    // ---- epilogue ----
    const int g = lane >> 2, tc = lane & 3;
    #pragma unroll
    for (int i = 0; i < 4; i++) {
        #pragma unroll
        for (int j = 0; j < 4; j++) {
            const int col  = bn + wn * 32 + j * 8 + tc * 2;
            const float2 b2 = *(const float2*)&bias[col];
            #pragma unroll
            for (int h = 0; h < 2; h++) {
                const int row = bm + wm * 64 + i * 16 + g + h * 8;
                float v0 = acc[i][j][2 * h]     + b2.x;
                float v1 = acc[i][j][2 * h + 1] + b2.y;
                if (RESID) {
                    float2 rv = *(const float2*)&R[(size_t)row * N + col];
                    v0 += rv.x; v1 += rv.y;
                }
                if (GELU_ACT) { v0 = gelu_f(v0); v1 = gelu_f(v1); }
                if (OUTF32) {
                    float2 o; o.x = v0; o.y = v1;
                    *(float2*)&Cf[(size_t)row * N + col] = o;
                }
                if (SPLIT) {
                    __nv_bfloat16 h0, h1, l0, l1;
                    split2(v0, h0, l0); split2(v1, h1, l1);
                    __nv_bfloat162 ph; ph.x = h0; ph.y = h1;
                    __nv_bfloat162 pl; pl.x = l0; pl.y = l1;
                    *(__nv_bfloat162*)&Ch[(size_t)row * N + col] = ph;
                    *(__nv_bfloat162*)&Cl[(size_t)row * N + col] = pl;
                }
            }
        }
    }
}

// ---------------- flash attention (fp32, 64x64 tiles, online softmax) -------
#define ALD 68
#define ATT_SMEM (4 * 64 * ALD * 4)

__global__ void __launch_bounds__(256) attn_kernel(
    const float* __restrict__ qkv, __nv_bfloat16* __restrict__ ctxh,
    __nv_bfloat16* __restrict__ ctxl)
{
    extern __shared__ float sm[];
    float* Qs = sm;
    float* Ks = Qs + 64 * ALD;
    float* Vs = Ks + 64 * ALD;
    float* Ps = Vs + 64 * ALD;

    const int qt = blockIdx.x, h = blockIdx.y, b = blockIdx.z;
    const int q0 = qt * 64;
    const int tid = threadIdx.x;
    const int tx = tid & 15, ty = tid >> 4;

    const size_t rowbase = (size_t)(b * SEQ) * (3 * D_MODEL);
    const int qcol = h * HD;
    const int kcol = D_MODEL + h * HD;
    const int vcol = 2 * D_MODEL + h * HD;

    #pragma unroll
    for (int t = 0; t < 4; t++) {
        int lin = tid + t * 256;
        int r = lin >> 4, d4 = (lin & 15) << 2;
        float4 v = *(const float4*)&qkv[rowbase + (size_t)(q0 + r) * (3 * D_MODEL) + qcol + d4];
        v.x *= 0.03125f; v.y *= 0.03125f; v.z *= 0.03125f; v.w *= 0.03125f;
        *(float4*)&Qs[r * ALD + d4] = v;
    }

    float m[4], l[4], acc[4][4];
    #pragma unroll
    for (int i = 0; i < 4; i++) {
        m[i] = -INFINITY; l[i] = 0.f;
        #pragma unroll
        for (int j = 0; j < 4; j++) acc[i][j] = 0.f;
    }

    for (int jt = 0; jt <= qt; jt++) {
        const int j0 = jt * 64;
        #pragma unroll
        for (int t = 0; t < 4; t++) {
            int lin = tid + t * 256;
            int r = lin >> 4, d4 = (lin & 15) << 2;
            size_t base = rowbase + (size_t)(j0 + r) * (3 * D_MODEL);
            *(float4*)&Ks[r * ALD + d4] = *(const float4*)&qkv[base + kcol + d4];
            *(float4*)&Vs[r * ALD + d4] = *(const float4*)&qkv[base + vcol + d4];
        }
        __syncthreads();

        float s[4][4];
        #pragma unroll
        for (int i = 0; i < 4; i++)
            #pragma unroll
            for (int j = 0; j < 4; j++) s[i][j] = 0.f;

        #pragma unroll 4
        for (int d = 0; d < HD; d += 4) {
            float4 qv[4], kv[4];
            #pragma unroll
            for (int i = 0; i < 4; i++) qv[i] = *(const float4*)&Qs[(ty + 16 * i) * ALD + d];
            #pragma unroll
            for (int j = 0; j < 4; j++) kv[j] = *(const float4*)&Ks[(tx + 16 * j) * ALD + d];
            #pragma unroll
            for (int i = 0; i < 4; i++)
                #pragma unroll
                for (int j = 0; j < 4; j++) {
                    s[i][j] = fmaf(qv[i].x, kv[j].x, s[i][j]);
                    s[i][j] = fmaf(qv[i].y, kv[j].y, s[i][j]);
                    s[i][j] = fmaf(qv[i].z, kv[j].z, s[i][j]);
                    s[i][j] = fmaf(qv[i].w, kv[j].w, s[i][j]);
                }
        }

        if (jt == qt) {
            #pragma unroll
            for (int i = 0; i < 4; i++)
                #pragma unroll
                for (int j = 0; j < 4; j++)
                    if ((j0 + tx + 16 * j) > (q0 + ty + 16 * i)) s[i][j] = -INFINITY;
        }

        #pragma unroll
        for (int i = 0; i < 4; i++) {
            float mx = fmaxf(fmaxf(s[i][0], s[i][1]), fmaxf(s[i][2], s[i][3]));
            #pragma unroll
            for (int off = 8; off; off >>= 1)
                mx = fmaxf(mx, __shfl_xor_sync(0xffffffffu, mx, off));
            const float mn = fmaxf(m[i], mx);
            const float alpha = expf(m[i] - mn);
            float p[4], psum = 0.f;
            #pragma unroll
            for (int j = 0; j < 4; j++) { p[j] = expf(s[i][j] - mn); psum += p[j]; }
            #pragma unroll
            for (int off = 8; off; off >>= 1)
                psum += __shfl_xor_sync(0xffffffffu, psum, off);
            l[i] = l[i] * alpha + psum;
            m[i] = mn;
            #pragma unroll
            for (int j = 0; j < 4; j++) {
                acc[i][j] *= alpha;
                Ps[(ty + 16 * i) * ALD + tx + 16 * j] = p[j];
            }
        }
        __syncthreads();

        #pragma unroll 4
        for (int kk = 0; kk < 64; kk += 4) {
            float4 p4[4];
            #pragma unroll
            for (int i = 0; i < 4; i++) p4[i] = *(const float4*)&Ps[(ty + 16 * i) * ALD + kk];
            float4 v0 = *(const float4*)&Vs[(kk + 0) * ALD + tx * 4];
            float4 v1 = *(const float4*)&Vs[(kk + 1) * ALD + tx * 4];
            float4 v2 = *(const float4*)&Vs[(kk + 2) * ALD + tx * 4];
            float4 v3 = *(const float4*)&Vs[(kk + 3) * ALD + tx * 4];
            float vr[4][4] = {{v0.x, v0.y, v0.z, v0.w}, {v1.x, v1.y, v1.z, v1.w},
                              {v2.x, v2.y, v2.z, v2.w}, {v3.x, v3.y, v3.z, v3.w}};
            #pragma unroll
            for (int i = 0; i < 4; i++) {
                float pr[4] = {p4[i].x, p4[i].y, p4[i].z, p4[i].w};
                #pragma unroll
                for (int j = 0; j < 4; j++) {
                    acc[i][j] = fmaf(pr[0], vr[0][j], acc[i][j]);
                    acc[i][j] = fmaf(pr[1], vr[1][j], acc[i][j]);
                    acc[i][j] = fmaf(pr[2], vr[2][j], acc[i][j]);
                    acc[i][j] = fmaf(pr[3], vr[3][j], acc[i][j]);
                }
            }
        }
        __syncthreads();
    }

    #pragma unroll
    for (int i = 0; i < 4; i++) {
        const float inv = 1.f / l[i];
        float o0 = acc[i][0] * inv, o1 = acc[i][1] * inv;
        float o2 = acc[i][2] * inv, o3 = acc[i][3] * inv;
        const size_t tok = (size_t)(b * SEQ + q0 + ty + 16 * i);
        const size_t base = tok * D_MODEL + h * HD + tx * 4;
        __nv_bfloat16 h0, h1, h2, h3, l0, l1, l2, l3;
        split2(o0, h0, l0); split2(o1, h1, l1);
        split2(o2, h2, l2); split2(o3, h3, l3);
        __nv_bfloat162 p;
        p.x = h0; p.y = h1; *(__nv_bfloat162*)&ctxh[base]     = p;
        p.x = h2; p.y = h3; *(__nv_bfloat162*)&ctxh[base + 2] = p;
        p.x = l0; p.y = l1; *(__nv_bfloat162*)&ctxl[base]     = p;
        p.x = l2; p.y = l3; *(__nv_bfloat162*)&ctxl[base + 2] = p;
    }
}

// ---------------- host launch ----------------
extern "C" void kernel_launch(void* const* d_in, const int* in_sizes, int n_in,
                              void* d_out, int out_size)
{
    const float* x    = (const float*)d_in[0];
    const float* wqkv = (const float*)d_in[1];
    const float* bqkv = (const float*)d_in[2];
    const float* wo   = (const float*)d_in[3];
    const float* bo   = (const float*)d_in[4];
    const float* g1   = (const float*)d_in[5];
    const float* be1  = (const float*)d_in[6];
    const float* g2   = (const float*)d_in[7];
    const float* be2  = (const float*)d_in[8];
    const float* w1   = (const float*)d_in[9];
    const float* b1   = (const float*)d_in[10];
    const float* w2   = (const float*)d_in[11];
    const float* b2   = (const float*)d_in[12];
    float* out = (float*)d_out;

    __nv_bfloat16 *lnh, *lnl, *ctxh, *ctxl, *hidh, *hidl;
    __nv_bfloat16 *wqkvh, *wqkvl, *woh, *wol, *w1h, *w1l, *w2h, *w2l;
    float *qkv, *x1;
    cudaGetSymbolAddress((void**)&lnh,  g_lnh);
    cudaGetSymbolAddress((void**)&lnl,  g_lnl);
    cudaGetSymbolAddress((void**)&qkv,  g_qkv);
    cudaGetSymbolAddress((void**)&ctxh, g_ctxh);
    cudaGetSymbolAddress((void**)&ctxl, g_ctxl);
    cudaGetSymbolAddress((void**)&x1,   g_x1);
    cudaGetSymbolAddress((void**)&hidh, g_hidh);
    cudaGetSymbolAddress((void**)&hidl, g_hidl);
    cudaGetSymbolAddress((void**)&wqkvh, g_wqkvh);
    cudaGetSymbolAddress((void**)&wqkvl, g_wqkvl);
    cudaGetSymbolAddress((void**)&woh,  g_woh);
    cudaGetSymbolAddress((void**)&wol,  g_wol);
    cudaGetSymbolAddress((void**)&w1h,  g_w1h);
    cudaGetSymbolAddress((void**)&w1l,  g_w1l);
    cudaGetSymbolAddress((void**)&w2h,  g_w2h);
    cudaGetSymbolAddress((void**)&w2l,  g_w2l);

    cudaFuncSetAttribute(attn_kernel, cudaFuncAttributeMaxDynamicSharedMemorySize, ATT_SMEM);
    cudaFuncSetAttribute(mma_gemm<false, false, true, false>,
                         cudaFuncAttributeMaxDynamicSharedMemorySize, 2 * GSTAGE);
    cudaFuncSetAttribute(mma_gemm<false, true, true, false>,
                         cudaFuncAttributeMaxDynamicSharedMemorySize, 2 * GSTAGE);
    cudaFuncSetAttribute(mma_gemm<true, false, false, true>,
                         cudaFuncAttributeMaxDynamicSharedMemorySize, 2 * GSTAGE);

    // weight splits (fp32 -> bf16 hi/lo)
    split_kernel<<<(D_MODEL * 3 * D_MODEL / 4 + 255) / 256, 256>>>(wqkv, wqkvh, wqkvl, D_MODEL * 3 * D_MODEL / 4);
    split_kernel<<<(D_MODEL * D_MODEL / 4 + 255) / 256, 256>>>(wo, woh, wol, D_MODEL * D_MODEL / 4);
    split_kernel<<<(D_MODEL * D_MID / 4 + 255) / 256, 256>>>(w1, w1h, w1l, D_MODEL * D_MID / 4);
    split_kernel<<<(D_MID * D_MODEL / 4 + 255) / 256, 256>>>(w2, w2h, w2l, D_MID * D_MODEL / 4);

    // 1. LN1 -> hi/lo
    ln_kernel<<<NTOK, 256>>>(x, g1, be1, lnh, lnl);
    // 2. QKV projection (f32 out + bias)
    mma_gemm<false, false, true, false><<<dim3(3 * D_MODEL / 128, NTOK / 128), 256, 2 * GSTAGE>>>(
        lnh, lnl, wqkvh, wqkvl, bqkv, nullptr, qkv, nullptr, nullptr,
        NTOK, 3 * D_MODEL, D_MODEL);
    // 3. attention -> ctx hi/lo
    attn_kernel<<<dim3(SEQ / 64, NH, BATCH), 256, ATT_SMEM>>>(qkv, ctxh, ctxl);
    // 4. O projection + residual: x1 = x + ctx@wo + bo (f32)
    mma_gemm<false, true, true, false><<<dim3(D_MODEL / 128, NTOK / 128), 256, 2 * GSTAGE>>>(
        ctxh, ctxl, woh, wol, bo, x, x1, nullptr, nullptr,
        NTOK, D_MODEL, D_MODEL);
    // 5. LN2 -> hi/lo
    ln_kernel<<<NTOK, 256>>>(x1, g2, be2, lnh, lnl);
    // 6. FFN1 + gelu -> hid hi/lo
    mma_gemm<true, false, false, true><<<dim3(D_MID / 128, NTOK / 128), 256, 2 * GSTAGE>>>(
        lnh, lnl, w1h, w1l, b1, nullptr, nullptr, hidh, hidl,
        NTOK, D_MID, D_MODEL);
    // 7. FFN2 + residual -> out (f32)
    mma_gemm<false, true, true, false><<<dim3(D_MODEL / 128, NTOK / 128), 256, 2 * GSTAGE>>>(
        hidh, hidl, w2h, w2l, b2, x1, out, nullptr, nullptr,
        NTOK, D_MODEL, D_MID);
}

// round 5
// speedup vs baseline: 2.2397x; 1.2508x over previous
#include <cuda_runtime.h>
#include <cuda_bf16.h>
#include <math.h>

#define D_MODEL 1024
#define D_MID   4096
#define SEQ     2048
#define BATCH   2
#define NTOK    (BATCH * SEQ)   // 4096
#define NH      16
#define HD      64

// log2(e) / sqrt(D_MODEL) = 1.4426950408889634 / 32
#define QSCALE 0.045084220027780106f

// ---------------- persistent scratch ----------------
__device__ __nv_bfloat16 g_lnh [NTOK * D_MODEL];
__device__ __nv_bfloat16 g_lnl [NTOK * D_MODEL];
__device__ __nv_bfloat16 g_qh  [NTOK * D_MODEL];
__device__ __nv_bfloat16 g_ql  [NTOK * D_MODEL];
__device__ __nv_bfloat16 g_kh  [NTOK * D_MODEL];
__device__ __nv_bfloat16 g_kl  [NTOK * D_MODEL];
__device__ __nv_bfloat16 g_vh  [NTOK * D_MODEL];
__device__ __nv_bfloat16 g_vl  [NTOK * D_MODEL];
__device__ __nv_bfloat16 g_ctxh[NTOK * D_MODEL];
__device__ __nv_bfloat16 g_ctxl[NTOK * D_MODEL];
__device__ float         g_x1  [NTOK * D_MODEL];
__device__ __nv_bfloat16 g_hidh[NTOK * D_MID];
__device__ __nv_bfloat16 g_hidl[NTOK * D_MID];
__device__ __nv_bfloat16 g_wqkvh[D_MODEL * 3 * D_MODEL];
__device__ __nv_bfloat16 g_wqkvl[D_MODEL * 3 * D_MODEL];
__device__ __nv_bfloat16 g_woh [D_MODEL * D_MODEL];
__device__ __nv_bfloat16 g_wol [D_MODEL * D_MODEL];
__device__ __nv_bfloat16 g_w1h [D_MODEL * D_MID];
__device__ __nv_bfloat16 g_w1l [D_MODEL * D_MID];
__device__ __nv_bfloat16 g_w2h [D_MID * D_MODEL];
__device__ __nv_bfloat16 g_w2l [D_MID * D_MODEL];

// ---------------- helpers ----------------
__device__ __forceinline__ void split2(float v, __nv_bfloat16& h, __nv_bfloat16& l)
{
    h = __float2bfloat16(v);
    l = __float2bfloat16(v - __bfloat162float(h));
}

__device__ __forceinline__ unsigned smem_u32(const void* p)
{
    return (unsigned)__cvta_generic_to_shared(p);
}

// pack two fp32 into bf16x2: e0 -> low 16, e1 -> high 16
__device__ __forceinline__ unsigned pack_bf16x2(float e0, float e1)
{
    unsigned d;
    asm("cvt.rn.bf16x2.f32 %0, %1, %2;" : "=r"(d) : "f"(e1), "f"(e0));
    return d;
}

__device__ __forceinline__ void split_pack(float e0, float e1, unsigned& h, unsigned& l)
{
    h = pack_bf16x2(e0, e1);
    __nv_bfloat162 hb = *(__nv_bfloat162*)&h;
    l = pack_bf16x2(e0 - __bfloat162float(hb.x), e1 - __bfloat162float(hb.y));
}

// fast 2^x for x <= 0, FFMA-only (avoids MUFU throughput wall)
__device__ __forceinline__ float fexp2(float x)
{
    x = fmaxf(x, -126.f);
    float fl = floorf(x);
    float f = x - fl;
    float p = 1.5403530393381609e-4f;
    p = fmaf(p, f, 1.3333558146428443e-3f);
    p = fmaf(p, f, 9.618129107628477e-3f);
    p = fmaf(p, f, 5.550410866482158e-2f);
    p = fmaf(p, f, 2.402265069591007e-1f);
    p = fmaf(p, f, 6.931471805599453e-1f);
    p = fmaf(p, f, 1.0f);
    int e = (int)fl;
    return __int_as_float((e + 127) << 23) * p;
}

#define CP16(dst_u32, src_ptr) \
    asm volatile("cp.async.cg.shared.global [%0], [%1], 16;\n" :: "r"(dst_u32), "l"(src_ptr))
#define CP_COMMIT() asm volatile("cp.async.commit_group;\n")
#define CP_WAIT(n)  asm volatile("cp.async.wait_group %0;\n" :: "n"(n))

#define LDSM4(r, addr) \
    asm volatile("ldmatrix.sync.aligned.m8n8.x4.shared.b16 {%0,%1,%2,%3},[%4];" \
        : "=r"((r)[0]), "=r"((r)[1]), "=r"((r)[2]), "=r"((r)[3]) : "r"(addr))
#define LDSM4T(r, addr) \
    asm volatile("ldmatrix.sync.aligned.m8n8.x4.trans.shared.b16 {%0,%1,%2,%3},[%4];" \
        : "=r"((r)[0]), "=r"((r)[1]), "=r"((r)[2]), "=r"((r)[3]) : "r"(addr))

#define MMA_BF16(d, a, b0, b1) \
    asm volatile("mma.sync.aligned.m16n8k16.row.col.f32.bf16.bf16.f32 " \
        "{%0,%1,%2,%3},{%4,%5,%6,%7},{%8,%9},{%0,%1,%2,%3};" \
        : "+f"((d)[0]), "+f"((d)[1]), "+f"((d)[2]), "+f"((d)[3]) \
        : "r"((a)[0]), "r"((a)[1]), "r"((a)[2]), "r"((a)[3]), "r"(b0), "r"(b1))

// ---------------- fp32 -> bf16 hi/lo split (weights) ----------------
__global__ void __launch_bounds__(256) split_kernel(
    const float* __restrict__ x, __nv_bfloat16* __restrict__ hi,
    __nv_bfloat16* __restrict__ lo, int n4)
{
    int i = blockIdx.x * 256 + threadIdx.x;
    if (i >= n4) return;
    float4 v = ((const float4*)x)[i];
    __nv_bfloat16 h0, h1, h2, h3, l0, l1, l2, l3;
    split2(v.x, h0, l0); split2(v.y, h1, l1);
    split2(v.z, h2, l2); split2(v.w, h3, l3);
    __nv_bfloat162 a, b;
    a.x = h0; a.y = h1; b.x = h2; b.y = h3;
    ((__nv_bfloat162*)hi)[2 * i]     = a;
    ((__nv_bfloat162*)hi)[2 * i + 1] = b;
    a.x = l0; a.y = l1; b.x = l2; b.y = l3;
    ((__nv_bfloat162*)lo)[2 * i]     = a;
    ((__nv_bfloat162*)lo)[2 * i + 1] = b;
}

// ---------------- layernorm -> bf16 hi/lo ----------------
__global__ void __launch_bounds__(256) ln_kernel(
    const float* __restrict__ x, const float* __restrict__ g,
    const float* __restrict__ bta, __nv_bfloat16* __restrict__ hi,
    __nv_bfloat16* __restrict__ lo)
{
    __shared__ float rbuf[16];
    const int row = blockIdx.x;
    const int tid = threadIdx.x;
    const float4* xr = (const float4*)(x + (size_t)row * D_MODEL);
    float4 v = xr[tid];
    float s  = v.x + v.y + v.z + v.w;
    float sq = v.x*v.x + v.y*v.y + v.z*v.z + v.w*v.w;
    #pragma unroll
    for (int off = 16; off; off >>= 1) {
        s  += __shfl_xor_sync(0xffffffffu, s,  off);
        sq += __shfl_xor_sync(0xffffffffu, sq, off);
    }
    const int wid = tid >> 5, lane = tid & 31;
    if (lane == 0) { rbuf[wid] = s; rbuf[8 + wid] = sq; }
    __syncthreads();
    if (tid < 32) {
        float a  = (lane < 8) ? rbuf[lane]     : 0.f;
        float b2 = (lane < 8) ? rbuf[8 + lane] : 0.f;
        #pragma unroll
        for (int off = 4; off; off >>= 1) {
            a  += __shfl_xor_sync(0xffffffffu, a,  off);
            b2 += __shfl_xor_sync(0xffffffffu, b2, off);
        }
        if (lane == 0) { rbuf[0] = a; rbuf[8] = b2; }
    }
    __syncthreads();
    const float mu  = rbuf[0] * (1.f / D_MODEL);
    const float var = rbuf[8] * (1.f / D_MODEL) - mu * mu;
    const float rs  = rsqrtf(var + 1e-5f);
    float4 gv = ((const float4*)g)[tid];
    float4 bv = ((const float4*)bta)[tid];
    float o0 = (v.x - mu) * rs * gv.x + bv.x;
    float o1 = (v.y - mu) * rs * gv.y + bv.y;
    float o2 = (v.z - mu) * rs * gv.z + bv.z;
    float o3 = (v.w - mu) * rs * gv.w + bv.w;
    __nv_bfloat16 h0, h1, h2, h3, l0, l1, l2, l3;
    split2(o0, h0, l0); split2(o1, h1, l1);
    split2(o2, h2, l2); split2(o3, h3, l3);
    const size_t base = (size_t)row * D_MODEL + tid * 4;
    __nv_bfloat162 p;
    p.x = h0; p.y = h1; *(__nv_bfloat162*)&hi[base]     = p;
    p.x = h2; p.y = h3; *(__nv_bfloat162*)&hi[base + 2] = p;
    p.x = l0; p.y = l1; *(__nv_bfloat162*)&lo[base]     = p;
    p.x = l2; p.y = l3; *(__nv_bfloat162*)&lo[base + 2] = p;
}

// ---------------- gelu ----------------
__device__ __forceinline__ float gelu_f(float x)
{
    const float c = 0.7978845608028654f;
    float x3 = x * x * x;
    return 0.5f * x * (1.f + tanhf(c * (x + 0.044715f * x3)));
}

// ---------------- bf16x3 tensor-core GEMM ----------------
// MODE 0: fp32 out (+RESID).  MODE 1: bf16 hi/lo split out.  MODE 2: qkv split
// into per-head [b,h,l,d] hi/lo buffers, Q pre-scaled by QSCALE.
#define GSTAGE 65536
#define GSM_AH 0
#define GSM_AL 16384
#define GSM_BH 32768
#define GSM_BL 49152

template<int MODE, bool GELU_ACT, bool RESID>
__global__ void __launch_bounds__(256) mma_gemm(
    const __nv_bfloat16* __restrict__ Ah, const __nv_bfloat16* __restrict__ Al,
    const __nv_bfloat16* __restrict__ Bh, const __nv_bfloat16* __restrict__ Bl,
    const float* __restrict__ bias, const float* __restrict__ R,
    float* __restrict__ Cf, __nv_bfloat16* __restrict__ Ch,
    __nv_bfloat16* __restrict__ Cl,
    __nv_bfloat16* __restrict__ Kh, __nv_bfloat16* __restrict__ Kl,
    __nv_bfloat16* __restrict__ Vh, __nv_bfloat16* __restrict__ Vl,
    int M, int N, int K)
{
    extern __shared__ char smraw[];
    const unsigned sbase = smem_u32(smraw);
    const int tid = threadIdx.x, lane = tid & 31, wid = tid >> 5;
    const int wm = wid & 1, wn = wid >> 1;
    const int bm = blockIdx.y * 128, bn = blockIdx.x * 128;

    float acc[4][4][4];
    #pragma unroll
    for (int i = 0; i < 4; i++)
        #pragma unroll
        for (int j = 0; j < 4; j++)
            #pragma unroll
            for (int q = 0; q < 4; q++) acc[i][j][q] = 0.f;

    const int ar = tid >> 1, ac = (tid & 1) * 4;
    const int br = tid >> 2, bc = (tid & 3) * 4;
    unsigned aoff[4], boff[4];
    #pragma unroll
    for (int i = 0; i < 4; i++) {
        aoff[i] = (unsigned)(ar * 128 + (((ac + i) ^ (ar & 7)) << 4));
        boff[i] = (unsigned)(br * 256 + (((bc + i) ^ (br & 7)) << 4));
    }
    const __nv_bfloat16* agh = Ah + (size_t)(bm + ar) * K;
    const __nv_bfloat16* agl = Al + (size_t)(bm + ar) * K;

    auto load_stage = [&](int s, int k0) {
        unsigned sb = sbase + s * GSTAGE;
        const __nv_bfloat16* bgh = Bh + (size_t)(k0 + br) * N + bn;
        const __nv_bfloat16* bgl = Bl + (size_t)(k0 + br) * N + bn;
        #pragma unroll
        for (int i = 0; i < 4; i++) {
            CP16(sb + GSM_AH + aoff[i], agh + k0 + (ac + i) * 8);
            CP16(sb + GSM_AL + aoff[i], agl + k0 + (ac + i) * 8);
            CP16(sb + GSM_BH + boff[i], bgh + (bc + i) * 8);
            CP16(sb + GSM_BL + boff[i], bgl + (bc + i) * 8);
        }
        CP_COMMIT();
    };

    const int a_row_l = lane & 15;
    const int hi_half = (lane >> 4) & 1;
    int a_rowoff[4], a_rmask[4];
    #pragma unroll
    for (int i = 0; i < 4; i++) {
        int r = wm * 64 + i * 16 + a_row_l;
        a_rowoff[i] = r * 128;
        a_rmask[i]  = r & 7;
    }
    const int b_krow_l = lane & 15;
    int b_nchunk[2];
    #pragma unroll
    for (int p = 0; p < 2; p++) b_nchunk[p] = wn * 4 + p * 2 + hi_half;

    const int NIT = K >> 6;
    load_stage(0, 0);

    for (int it = 0; it < NIT; it++) {
        if (it + 1 < NIT) { load_stage((it + 1) & 1, (it + 1) << 6); CP_WAIT(1); }
        else              { CP_WAIT(0); }
        __syncthreads();

        unsigned sb = sbase + (it & 1) * GSTAGE;
        #pragma unroll
        for (int ks = 0; ks < 4; ks++) {
            unsigned ah[4][4], al[4][4], bh[2][4], bl[2][4];
            #pragma unroll
            for (int i = 0; i < 4; i++) {
                int chunk = 2 * ks + hi_half;
                unsigned off = a_rowoff[i] + ((chunk ^ a_rmask[i]) << 4);
                LDSM4(ah[i], sb + GSM_AH + off);
                LDSM4(al[i], sb + GSM_AL + off);
            }
            #pragma unroll
            for (int p = 0; p < 2; p++) {
                int kr = ks * 16 + b_krow_l;
                unsigned off = kr * 256 + ((b_nchunk[p] ^ (kr & 7)) << 4);
                LDSM4T(bh[p], sb + GSM_BH + off);
                LDSM4T(bl[p], sb + GSM_BL + off);
            }
            #pragma unroll
            for (int i = 0; i < 4; i++)
                #pragma unroll
                for (int j = 0; j < 4; j++) {
                    const int p = j >> 1, hf = (j & 1) * 2;
                    MMA_BF16(acc[i][j], ah[i], bh[p][hf], bh[p][hf + 1]);
                    MMA_BF16(acc[i][j], ah[i], bl[p][hf], bl[p][hf + 1]);
                    MMA_BF16(acc[i][j], al[i], bh[p][hf], bh[p][hf + 1]);
                }
        }
        __syncthreads();
    }

    // ---- epilogue ----
    const int g = lane >> 2, tc = lane & 3;
    #pragma unroll
    for (int i = 0; i < 4; i++) {
        #pragma unroll
        for (int j = 0; j < 4; j++) {
            const int col  = bn + wn * 32 + j * 8 + tc * 2;
            const float2 b2 = *(const float2*)&bias[col];
            #pragma unroll
            for (int h = 0; h < 2; h++) {
                const int row = bm + wm * 64 + i * 16 + g + h * 8;
                float v0 = acc[i][j][2 * h]     + b2.x;
                float v1 = acc[i][j][2 * h + 1] + b2.y;
                if (RESID) {
                    float2 rv = *(const float2*)&R[(size_t)row * N + col];
                    v0 += rv.x; v1 += rv.y;
                }
                if (GELU_ACT) { v0 = gelu_f(v0); v1 = gelu_f(v1); }
                if (MODE == 0) {
                    float2 o; o.x = v0; o.y = v1;
                    *(float2*)&Cf[(size_t)row * N + col] = o;
                }
                if (MODE == 1) {
                    unsigned ph, pl;
                    split_pack(v0, v1, ph, pl);
                    *(unsigned*)&Ch[(size_t)row * N + col] = ph;
                    *(unsigned*)&Cl[(size_t)row * N + col] = pl;
                }
                if (MODE == 2) {
                    const int which = col >> 10;
                    const int hh = (col >> 6) & (NH - 1);
                    const int dd = col & (HD - 1);
                    const int bb = row >> 11, ll = row & (SEQ - 1);
                    if (which == 0) { v0 *= QSCALE; v1 *= QSCALE; }
                    const size_t idx = ((size_t)(bb * NH + hh) * SEQ + ll) * HD + dd;
                    __nv_bfloat16* hp = (which == 0) ? Ch : (which == 1) ? Kh : Vh;
                    __nv_bfloat16* lp = (which == 0) ? Cl : (which == 1) ? Kl : Vl;
                    unsigned ph, pl;
                    split_pack(v0, v1, ph, pl);
                    *(unsigned*)&hp[idx] = ph;
                    *(unsigned*)&lp[idx] = pl;
                }
            }
        }
    }
}

// ---------------- tensor-core flash attention ----------------
// block = 128 q rows, 8 warps (16 q rows each), kv tile = 64.
// Q,K,V are bf16 hi/lo in [b,h,l,d] layout; Q pre-scaled by log2(e)/32.
// S = 3-term compensated QK^T mma; softmax fp32 (exp2 poly); PV 3-term mma.
#define ASM_QH 0
#define ASM_QL 16384
#define ASM_ST 32768     // stage base; each stage: KH 0, KL 8192, VH 16384, VL 24576
#define ASM_STAGE 32768
#define ATT_SMEM (ASM_ST + 2 * ASM_STAGE)   // 98304

__global__ void __launch_bounds__(256) attn_mma_kernel(
    const __nv_bfloat16* __restrict__ qh, const __nv_bfloat16* __restrict__ ql,
    const __nv_bfloat16* __restrict__ kh, const __nv_bfloat16* __restrict__ kl,
    const __nv_bfloat16* __restrict__ vh, const __nv_bfloat16* __restrict__ vl,
    __nv_bfloat16* __restrict__ ctxh, __nv_bfloat16* __restrict__ ctxl)
{
    extern __shared__ char smraw[];
    const unsigned sbase = smem_u32(smraw);
    const int qt = blockIdx.x, h = blockIdx.y, b = blockIdx.z;
    const int q0 = qt * 128;
    const int tid = threadIdx.x, lane = tid & 31, w = tid >> 5;
    const int g = lane >> 2, tc = lane & 3;

    const size_t headbase = (size_t)(b * NH + h) * SEQ;

    // ---- prologue: async-load Q tile (group 0) ----
    {
        const int r = tid >> 1, c0 = (tid & 1) * 4;
        const __nv_bfloat16* qgh = qh + (headbase + q0 + r) * HD;
        const __nv_bfloat16* qgl = ql + (headbase + q0 + r) * HD;
        #pragma unroll
        for (int c = 0; c < 4; c++) {
            unsigned off = r * 128 + (((c0 + c) ^ (r & 7)) << 4);
            CP16(sbase + ASM_QH + off, qgh + (c0 + c) * 8);
            CP16(sbase + ASM_QL + off, qgl + (c0 + c) * 8);
        }
        CP_COMMIT();
    }

    const int NT = 2 * qt + 2;
    const int kr = tid >> 2, kc0 = (tid & 3) * 2;

    auto load_stage = [&](int s, int j0) {
        unsigned sb = sbase + ASM_ST + s * ASM_STAGE;
        const size_t gbase = (headbase + j0 + kr) * HD;
        #pragma unroll
        for (int c = 0; c < 2; c++) {
            unsigned off = kr * 128 + (((kc0 + c) ^ (kr & 7)) << 4);
            const size_t gc = gbase + (kc0 + c) * 8;
            CP16(sb +         off, kh + gc);
            CP16(sb +  8192 + off, kl + gc);
            CP16(sb + 16384 + off, vh + gc);
            CP16(sb + 24576 + off, vl + gc);
        }
        CP_COMMIT();
    };

    load_stage(0, 0);          // group 1
    CP_WAIT(1);                // Q (group 0) complete
    __syncthreads();

    // ---- extract Q fragments (held in registers for whole kernel) ----
    unsigned qfh[4][4], qfl[4][4];
    {
        const int r  = w * 16 + (lane & 15);
        const int hh = lane >> 4;
        #pragma unroll
        for (int kc = 0; kc < 4; kc++) {
            unsigned off = r * 128 + (((2 * kc + hh) ^ (r & 7)) << 4);
            LDSM4(qfh[kc], sbase + ASM_QH + off);
            LDSM4(qfl[kc], sbase + ASM_QL + off);
        }
    }

    float m[2] = {-1e30f, -1e30f}, l[2] = {0.f, 0.f};
    float oacc[8][4];
    #pragma unroll
    for (int j = 0; j < 8; j++)
        #pragma unroll
        for (int e = 0; e < 4; e++) oacc[j][e] = 0.f;

    const int rbase = q0 + w * 16;

    for (int jt = 0; jt < NT; jt++) {
        if (jt + 1 < NT) { load_stage((jt + 1) & 1, (jt + 1) * 64); CP_WAIT(1); }
        else             { CP_WAIT(0); }
        __syncthreads();

        unsigned sb = sbase + ASM_ST + (jt & 1) * ASM_STAGE;
        const int j0 = jt * 64;

        // ---- S = Q K^T (3-term compensated) ----
        float sacc[8][4];
        #pragma unroll
        for (int j = 0; j < 8; j++)
            #pragma unroll
            for (int e = 0; e < 4; e++) sacc[j][e] = 0.f;

        #pragma unroll
        for (int kc = 0; kc < 4; kc++) {
            #pragma unroll
            for (int jp = 0; jp < 4; jp++) {
                const int r = jp * 16 + (lane & 15);
                const int c = 2 * kc + (lane >> 4);
                unsigned off = r * 128 + ((c ^ (r & 7)) << 4);
                unsigned kbh[4], kbl[4];
                LDSM4(kbh, sb + off);
                LDSM4(kbl, sb + 8192 + off);
                MMA_BF16(sacc[2 * jp],     qfh[kc], kbh[0], kbh[2]);
                MMA_BF16(sacc[2 * jp],     qfh[kc], kbl[0], kbl[2]);
                MMA_BF16(sacc[2 * jp],     qfl[kc], kbh[0], kbh[2]);
                MMA_BF16(sacc[2 * jp + 1], qfh[kc], kbh[1], kbh[3]);
                MMA_BF16(sacc[2 * jp + 1], qfh[kc], kbl[1], kbl[3]);
                MMA_BF16(sacc[2 * jp + 1], qfl[kc], kbh[1], kbh[3]);
            }
        }

        // ---- causal mask (only last two tiles can touch the diagonal) ----
        if (jt >= 2 * qt) {
            #pragma unroll
            for (int j = 0; j < 8; j++) {
                const int c0 = j0 + j * 8 + tc * 2;
                #pragma unroll
                for (int e = 0; e < 4; e++) {
                    const int col = c0 + (e & 1);
                    const int row = rbase + g + ((e >> 1) << 3);
                    if (col > row) sacc[j][e] = -1e30f;
                }
            }
        }

        // ---- online softmax (exp2 domain) ----
        #pragma unroll
        for (int rh = 0; rh < 2; rh++) {
            float mx = -1e30f;
            #pragma unroll
            for (int j = 0; j < 8; j++)
                mx = fmaxf(mx, fmaxf(sacc[j][2 * rh], sacc[j][2 * rh + 1]));
            mx = fmaxf(mx, __shfl_xor_sync(0xffffffffu, mx, 1));
            mx = fmaxf(mx, __shfl_xor_sync(0xffffffffu, mx, 2));
            const float mn = fmaxf(m[rh], mx);
            const float alpha = fexp2(m[rh] - mn);
            m[rh] = mn;
            float ls = 0.f;
            #pragma unroll
            for (int j = 0; j < 8; j++) {
                float p0 = fexp2(sacc[j][2 * rh]     - mn);
                float p1 = fexp2(sacc[j][2 * rh + 1] - mn);
                sacc[j][2 * rh] = p0; sacc[j][2 * rh + 1] = p1;
                ls += p0 + p1;
            }
            ls += __shfl_xor_sync(0xffffffffu, ls, 1);
            ls += __shfl_xor_sync(0xffffffffu, ls, 2);
            l[rh] = l[rh] * alpha + ls;
            #pragma unroll
            for (int j = 0; j < 8; j++) {
                oacc[j][2 * rh]     *= alpha;
                oacc[j][2 * rh + 1] *= alpha;
            }
        }

        // ---- O += P V (3-term compensated) ----
        #pragma unroll
        for (int kc = 0; kc < 4; kc++) {
            unsigned aph[4], apl[4];
            split_pack(sacc[2 * kc][0],     sacc[2 * kc][1],     aph[0], apl[0]);
            split_pack(sacc[2 * kc][2],     sacc[2 * kc][3],     aph[1], apl[1]);
            split_pack(sacc[2 * kc + 1][0], sacc[2 * kc + 1][1], aph[2], apl[2]);
            split_pack(sacc[2 * kc + 1][2], sacc[2 * kc + 1][3], aph[3], apl[3]);
            #pragma unroll
            for (int nc = 0; nc < 4; nc++) {
                const int r = kc * 16 + (lane & 15);
                const int c = 2 * nc + (lane >> 4);
                unsigned off = r * 128 + ((c ^ (r & 7)) << 4);
                unsigned vbh[4], vbl[4];
                LDSM4T(vbh, sb + 16384 + off);
                LDSM4T(vbl, sb + 24576 + off);
                MMA_BF16(oacc[2 * nc],     aph, vbh[0], vbh[1]);
                MMA_BF16(oacc[2 * nc],     aph, vbl[0], vbl[1]);
                MMA_BF16(oacc[2 * nc],     apl, vbh[0], vbh[1]);
                MMA_BF16(oacc[2 * nc + 1], aph, vbh[2], vbh[3]);
                MMA_BF16(oacc[2 * nc + 1], aph, vbl[2], vbl[3]);
                MMA_BF16(oacc[2 * nc + 1], apl, vbh[2], vbh[3]);
            }
        }
        __syncthreads();
    }

    // ---- epilogue: normalize, split hi/lo, store ctx [token, h*64+d] ----
    const float inv0 = 1.f / l[0], inv1 = 1.f / l[1];
    const size_t tok0 = (size_t)(b * SEQ + rbase + g);
    #pragma unroll
    for (int jo = 0; jo < 8; jo++) {
        const int col = h * HD + jo * 8 + tc * 2;
        unsigned ph, pl;
        split_pack(oacc[jo][0] * inv0, oacc[jo][1] * inv0, ph, pl);
        *(unsigned*)&ctxh[tok0 * D_MODEL + col] = ph;
        *(unsigned*)&ctxl[tok0 * D_MODEL + col] = pl;
        split_pack(oacc[jo][2] * inv1, oacc[jo][3] * inv1, ph, pl);
        *(unsigned*)&ctxh[(tok0 + 8) * D_MODEL + col] = ph;
        *(unsigned*)&ctxl[(tok0 + 8) * D_MODEL + col] = pl;
    }
}

// ---------------- host launch ----------------
extern "C" void kernel_launch(void* const* d_in, const int* in_sizes, int n_in,
                              void* d_out, int out_size)
{
    const float* x    = (const float*)d_in[0];
    const float* wqkv = (const float*)d_in[1];
    const float* bqkv = (const float*)d_in[2];
    const float* wo   = (const float*)d_in[3];
    const float* bo   = (const float*)d_in[4];
    const float* g1   = (const float*)d_in[5];
    const float* be1  = (const float*)d_in[6];
    const float* g2   = (const float*)d_in[7];
    const float* be2  = (const float*)d_in[8];
    const float* w1   = (const float*)d_in[9];
    const float* b1   = (const float*)d_in[10];
    const float* w2   = (const float*)d_in[11];
    const float* b2   = (const float*)d_in[12];
    float* out = (float*)d_out;

    __nv_bfloat16 *lnh, *lnl, *qh, *ql, *kh, *kl, *vh, *vl, *ctxh, *ctxl, *hidh, *hidl;
    __nv_bfloat16 *wqkvh, *wqkvl, *woh, *wol, *w1h, *w1l, *w2h, *w2l;
    float *x1;
    cudaGetSymbolAddress((void**)&lnh,  g_lnh);
    cudaGetSymbolAddress((void**)&lnl,  g_lnl);
    cudaGetSymbolAddress((void**)&qh,   g_qh);
    cudaGetSymbolAddress((void**)&ql,   g_ql);
    cudaGetSymbolAddress((void**)&kh,   g_kh);
    cudaGetSymbolAddress((void**)&kl,   g_kl);
    cudaGetSymbolAddress((void**)&vh,   g_vh);
    cudaGetSymbolAddress((void**)&vl,   g_vl);
    cudaGetSymbolAddress((void**)&ctxh, g_ctxh);
    cudaGetSymbolAddress((void**)&ctxl, g_ctxl);
    cudaGetSymbolAddress((void**)&x1,   g_x1);
    cudaGetSymbolAddress((void**)&hidh, g_hidh);
    cudaGetSymbolAddress((void**)&hidl, g_hidl);
    cudaGetSymbolAddress((void**)&wqkvh, g_wqkvh);
    cudaGetSymbolAddress((void**)&wqkvl, g_wqkvl);
    cudaGetSymbolAddress((void**)&woh,  g_woh);
    cudaGetSymbolAddress((void**)&wol,  g_wol);
    cudaGetSymbolAddress((void**)&w1h,  g_w1h);
    cudaGetSymbolAddress((void**)&w1l,  g_w1l);
    cudaGetSymbolAddress((void**)&w2h,  g_w2h);
    cudaGetSymbolAddress((void**)&w2l,  g_w2l);

    cudaFuncSetAttribute(attn_mma_kernel, cudaFuncAttributeMaxDynamicSharedMemorySize, ATT_SMEM);
    cudaFuncSetAttribute(mma_gemm<2, false, false>,
                         cudaFuncAttributeMaxDynamicSharedMemorySize, 2 * GSTAGE);
    cudaFuncSetAttribute(mma_gemm<0, false, true>,
                         cudaFuncAttributeMaxDynamicSharedMemorySize, 2 * GSTAGE);
    cudaFuncSetAttribute(mma_gemm<1, true, false>,
                         cudaFuncAttributeMaxDynamicSharedMemorySize, 2 * GSTAGE);

    split_kernel<<<(D_MODEL * 3 * D_MODEL / 4 + 255) / 256, 256>>>(wqkv, wqkvh, wqkvl, D_MODEL * 3 * D_MODEL / 4);
    split_kernel<<<(D_MODEL * D_MODEL / 4 + 255) / 256, 256>>>(wo, woh, wol, D_MODEL * D_MODEL / 4);
    split_kernel<<<(D_MODEL * D_MID / 4 + 255) / 256, 256>>>(w1, w1h, w1l, D_MODEL * D_MID / 4);
    split_kernel<<<(D_MID * D_MODEL / 4 + 255) / 256, 256>>>(w2, w2h, w2l, D_MID * D_MODEL / 4);

    // 1. LN1
    ln_kernel<<<NTOK, 256>>>(x, g1, be1, lnh, lnl);
    // 2. QKV projection -> split per-head q/k/v hi/lo (Q pre-scaled)
    mma_gemm<2, false, false><<<dim3(3 * D_MODEL / 128, NTOK / 128), 256, 2 * GSTAGE>>>(
        lnh, lnl, wqkvh, wqkvl, bqkv, nullptr, nullptr, qh, ql, kh, kl, vh, vl,
        NTOK, 3 * D_MODEL, D_MODEL);
    // 3. tensor-core flash attention -> ctx hi/lo
    attn_mma_kernel<<<dim3(SEQ / 128, NH, BATCH), 256, ATT_SMEM>>>(
        qh, ql, kh, kl, vh, vl, ctxh, ctxl);
    // 4. O projection + residual: x1 = x + ctx@wo + bo
    mma_gemm<0, false, true><<<dim3(D_MODEL / 128, NTOK / 128), 256, 2 * GSTAGE>>>(
        ctxh, ctxl, woh, wol, bo, x, x1, nullptr, nullptr, nullptr, nullptr, nullptr, nullptr,
        NTOK, D_MODEL, D_MODEL);
    // 5. LN2
    ln_kernel<<<NTOK, 256>>>(x1, g2, be2, lnh, lnl);
    // 6. FFN1 + gelu -> hid hi/lo
    mma_gemm<1, true, false><<<dim3(D_MID / 128, NTOK / 128), 256, 2 * GSTAGE>>>(
        lnh, lnl, w1h, w1l, b1, nullptr, nullptr, hidh, hidl, nullptr, nullptr, nullptr, nullptr,
        NTOK, D_MID, D_MODEL);
    // 7. FFN2 + residual -> out
    mma_gemm<0, false, true><<<dim3(D_MODEL / 128, NTOK / 128), 256, 2 * GSTAGE>>>(
        hidh, hidl, w2h, w2l, b2, x1, out, nullptr, nullptr, nullptr, nullptr, nullptr, nullptr,
        NTOK, D_MODEL, D_MID);
}